// round 12
// baseline (speedup 1.0000x reference)
#include <cuda_runtime.h>
#include <cuda_fp16.h>
#include <cstdint>

#define NN 200000
#define NG 2048
#define INF 256
#define HID 512
#define OUTF 256

// ---------------- scratch (__device__ globals: allocation-free rule) ----------
__device__ __half g_x16[(size_t)NN * INF];
__device__ __half g_h1[(size_t)NN * HID];
__device__ __half g_h2[(size_t)NN * HID];
__device__ __half g_pooled[NG * HID];
__device__ __half g_g1[NG * HID];
__device__ __half g_w1t[HID * INF];
__device__ __half g_w2t[HID * HID];
__device__ __half g_wg1t[HID * HID];
__device__ __half g_wg2t[OUTF * HID];

// ---------------- PTX helpers (portable sm_80+) ----------------
__device__ __forceinline__ uint32_t smem_u32(const void* p) {
    uint32_t a;
    asm("{ .reg .u64 t; cvta.to.shared.u64 t, %1; cvt.u32.u64 %0, t; }" : "=r"(a) : "l"(p));
    return a;
}
__device__ __forceinline__ void cp_async16(uint32_t dst, const void* src, int src_bytes) {
    asm volatile("cp.async.cg.shared.global [%0], [%1], 16, %2;"
                 :: "r"(dst), "l"(src), "r"(src_bytes) : "memory");
}
__device__ __forceinline__ void cp_commit() {
    asm volatile("cp.async.commit_group;" ::: "memory");
}
__device__ __forceinline__ void cp_wait1() {
    asm volatile("cp.async.wait_group 1;" ::: "memory");
}
__device__ __forceinline__ void ldsm4(uint32_t* r, uint32_t addr) {
    asm volatile("ldmatrix.sync.aligned.m8n8.x4.shared.b16 {%0,%1,%2,%3}, [%4];"
                 : "=r"(r[0]), "=r"(r[1]), "=r"(r[2]), "=r"(r[3]) : "r"(addr));
}
__device__ __forceinline__ void ldsm2(uint32_t* r, uint32_t addr) {
    asm volatile("ldmatrix.sync.aligned.m8n8.x2.shared.b16 {%0,%1}, [%2];"
                 : "=r"(r[0]), "=r"(r[1]) : "r"(addr));
}
__device__ __forceinline__ void mma16816(float* d, const uint32_t* a, const uint32_t* b) {
    asm volatile(
        "mma.sync.aligned.m16n8k16.row.col.f32.f16.f16.f32 "
        "{%0,%1,%2,%3}, {%4,%5,%6,%7}, {%8,%9}, {%0,%1,%2,%3};"
        : "+f"(d[0]), "+f"(d[1]), "+f"(d[2]), "+f"(d[3])
        : "r"(a[0]), "r"(a[1]), "r"(a[2]), "r"(a[3]), "r"(b[0]), "r"(b[1]));
}

// ---------------------------------------------------------------------------
// fp16 tensor-core GEMM with cp.async 3-stage pipeline (R7 known-good config;
// single-buffered register fragments — double-buffering spilled under the
// 128-reg occupancy-2 cap and regressed).
// C[M,N] = act(A[M,K] @ Bt^T + bias);  A,Bt fp16 row-major [*,K].
// Tile BM=128, BN=128, BK=64; 256 threads (8 warps, 2x4); 3 x 32KB smem.
// ---------------------------------------------------------------------------
#define HG_STAGE 32768
#define HG_SMEM  (3 * HG_STAGE)

template <bool RELU, bool OUT_HALF>
__global__ __launch_bounds__(256, 2) void hgemm(
    const __half* __restrict__ A, const __half* __restrict__ Bt,
    const float* __restrict__ bias, void* __restrict__ Cv,
    int M, int N, int K)
{
    extern __shared__ char smem[];
    const uint32_t sbase = smem_u32(smem);
    const int tid = threadIdx.x, wid = tid >> 5, lane = tid & 31;
    const int wm = wid >> 2, wn = wid & 3;      // warp grid 2 x 4 (64x32 per warp)
    const int rowBase = blockIdx.y * 128, colBase = blockIdx.x * 128;

    float acc[4][4][4];
#pragma unroll
    for (int i = 0; i < 4; ++i)
#pragma unroll
        for (int j = 0; j < 4; ++j)
#pragma unroll
            for (int k = 0; k < 4; ++k) acc[i][j][k] = 0.0f;

    const int a_row = lane & 15;
    const int a_kb  = (lane >> 4) << 4;
    const int b_row = lane & 7;
    const int b_kb  = (lane & 8) << 1;
    const int nc = K >> 6;

    auto issue = [&](int c) {
        const int stage = c % 3;
        const uint32_t stA = sbase + stage * HG_STAGE;
        const uint32_t stB = stA + 16384;
        const int k0 = c << 6;
#pragma unroll
        for (int j = 0; j < 4; ++j) {           // A: 128 rows x 128B
            int idx = j * 256 + tid, r = idx >> 3, q = idx & 7;
            int gr = rowBase + r;
            int sz = (gr < M) ? 16 : 0;
            if (gr >= M) gr = M - 1;            // safe address, zero-filled
            uint32_t dst = stA + r * 128 + ((q * 16) ^ ((r & 7) << 4));
            cp_async16(dst, A + (size_t)gr * K + k0 + q * 8, sz);
        }
#pragma unroll
        for (int j = 0; j < 4; ++j) {           // B: 128 rows x 128B
            int idx = j * 256 + tid, r = idx >> 3, q = idx & 7;
            uint32_t dst = stB + r * 128 + ((q * 16) ^ ((r & 7) << 4));
            cp_async16(dst, Bt + (size_t)(colBase + r) * K + k0 + q * 8, 16);
        }
        cp_commit();
    };

    issue(0);
    issue(1);

    for (int c = 0; c < nc; ++c) {
        cp_wait1();                 // stage c resident
        __syncthreads();

        const uint32_t baseA = sbase + (c % 3) * HG_STAGE;
        const uint32_t baseB = baseA + 16384;
#pragma unroll
        for (int ks = 0; ks < 4; ++ks) {
            uint32_t af[4][4], bf[4][2];
#pragma unroll
            for (int mt = 0; mt < 4; ++mt) {
                int row = wm * 64 + mt * 16 + a_row;
                ldsm4(af[mt], baseA + row * 128 + ((ks * 32 + a_kb) ^ ((row & 7) << 4)));
            }
#pragma unroll
            for (int nt = 0; nt < 4; ++nt) {
                int row = wn * 32 + nt * 8 + b_row;
                ldsm2(bf[nt], baseB + row * 128 + ((ks * 32 + b_kb) ^ ((row & 7) << 4)));
            }
#pragma unroll
            for (int mt = 0; mt < 4; ++mt)
#pragma unroll
                for (int nt = 0; nt < 4; ++nt)
                    mma16816(acc[mt][nt], af[mt], bf[nt]);
        }
        if (c + 2 < nc) issue(c + 2);
        // next iteration's __syncthreads (after cp_wait1) protects stage reuse
    }

    // ---- epilogue ----
    const int qr = lane >> 2, qc = (lane & 3) * 2;
#pragma unroll
    for (int nt = 0; nt < 4; ++nt) {
        const int cc = colBase + wn * 32 + nt * 8 + qc;
        const float2 bv = *reinterpret_cast<const float2*>(bias + cc);
#pragma unroll
        for (int mt = 0; mt < 4; ++mt) {
            const int r0 = rowBase + wm * 64 + mt * 16 + qr;
            float x0 = acc[mt][nt][0] + bv.x, x1 = acc[mt][nt][1] + bv.y;
            float x2 = acc[mt][nt][2] + bv.x, x3 = acc[mt][nt][3] + bv.y;
            if (RELU) {
                x0 = fmaxf(x0, 0.f); x1 = fmaxf(x1, 0.f);
                x2 = fmaxf(x2, 0.f); x3 = fmaxf(x3, 0.f);
            }
            if (OUT_HALF) {
                __half* C = (__half*)Cv;
                __half2 p0 = __floats2half2_rn(x0, x1);
                __half2 p1 = __floats2half2_rn(x2, x3);
                if (r0 < M)
                    *reinterpret_cast<uint32_t*>(C + (size_t)r0 * N + cc) =
                        *reinterpret_cast<uint32_t*>(&p0);
                if (r0 + 8 < M)
                    *reinterpret_cast<uint32_t*>(C + (size_t)(r0 + 8) * N + cc) =
                        *reinterpret_cast<uint32_t*>(&p1);
            } else {
                float* C = (float*)Cv;
                if (r0 < M)
                    *reinterpret_cast<float2*>(C + (size_t)r0 * N + cc) = make_float2(x0, x1);
                if (r0 + 8 < M)
                    *reinterpret_cast<float2*>(C + (size_t)(r0 + 8) * N + cc) = make_float2(x2, x3);
            }
        }
    }
}

// ---------------------------------------------------------------------------
__global__ void f2h(const float* __restrict__ in, __half* __restrict__ out, int n)
{
    int i = (blockIdx.x * blockDim.x + threadIdx.x) * 4;
    if (i < n) {
        float4 v = *reinterpret_cast<const float4*>(in + i);
        __half2 p0 = __floats2half2_rn(v.x, v.y);
        __half2 p1 = __floats2half2_rn(v.z, v.w);
        *reinterpret_cast<uint2*>(out + i) =
            make_uint2(*reinterpret_cast<uint32_t*>(&p0), *reinterpret_cast<uint32_t*>(&p1));
    }
}

__global__ void wtrans(const float* __restrict__ W, __half* __restrict__ out, int K, int N)
{
    int idx = blockIdx.x * blockDim.x + threadIdx.x;
    if (idx < N * K) {
        int n = idx / K, k = idx - n * K;
        out[idx] = __float2half_rn(W[(size_t)k * N + n]);
    }
}

// ---------------------------------------------------------------------------
// Segment-sum (sorted ids), fp16 in / fp32 accumulate / fp16 out.
// 4-row unroll with independent accumulators (MLP 4) to hide DRAM latency.
// ---------------------------------------------------------------------------
__global__ __launch_bounds__(128) void segment_pool(
    const __half* __restrict__ h, const int* __restrict__ seg,
    __half* __restrict__ pooled, int n_nodes)
{
    const int g = blockIdx.x;
    int lo = 0, hi = n_nodes;
    while (lo < hi) { int mid = (lo + hi) >> 1; if (seg[mid] < g) lo = mid + 1; else hi = mid; }
    const int start = lo;
    hi = n_nodes;
    while (lo < hi) { int mid = (lo + hi) >> 1; if (seg[mid] < g + 1) lo = mid + 1; else hi = mid; }
    const int end = lo;

    const int c = threadIdx.x << 2;
    float4 s0 = make_float4(0.f, 0.f, 0.f, 0.f);
    float4 s1 = make_float4(0.f, 0.f, 0.f, 0.f);
    float4 s2 = make_float4(0.f, 0.f, 0.f, 0.f);
    float4 s3 = make_float4(0.f, 0.f, 0.f, 0.f);
    int r = start;
    for (; r + 4 <= end; r += 4) {
        uint2 u0 = *reinterpret_cast<const uint2*>(h + (size_t)r * HID + c);
        uint2 u1 = *reinterpret_cast<const uint2*>(h + (size_t)(r + 1) * HID + c);
        uint2 u2 = *reinterpret_cast<const uint2*>(h + (size_t)(r + 2) * HID + c);
        uint2 u3 = *reinterpret_cast<const uint2*>(h + (size_t)(r + 3) * HID + c);
        float2 a0 = __half22float2(*reinterpret_cast<__half2*>(&u0.x));
        float2 a1 = __half22float2(*reinterpret_cast<__half2*>(&u0.y));
        float2 b0 = __half22float2(*reinterpret_cast<__half2*>(&u1.x));
        float2 b1 = __half22float2(*reinterpret_cast<__half2*>(&u1.y));
        float2 c0 = __half22float2(*reinterpret_cast<__half2*>(&u2.x));
        float2 c1 = __half22float2(*reinterpret_cast<__half2*>(&u2.y));
        float2 d0 = __half22float2(*reinterpret_cast<__half2*>(&u3.x));
        float2 d1 = __half22float2(*reinterpret_cast<__half2*>(&u3.y));
        s0.x += a0.x; s0.y += a0.y; s0.z += a1.x; s0.w += a1.y;
        s1.x += b0.x; s1.y += b0.y; s1.z += b1.x; s1.w += b1.y;
        s2.x += c0.x; s2.y += c0.y; s2.z += c1.x; s2.w += c1.y;
        s3.x += d0.x; s3.y += d0.y; s3.z += d1.x; s3.w += d1.y;
    }
    for (; r < end; ++r) {
        uint2 u0 = *reinterpret_cast<const uint2*>(h + (size_t)r * HID + c);
        float2 a0 = __half22float2(*reinterpret_cast<__half2*>(&u0.x));
        float2 a1 = __half22float2(*reinterpret_cast<__half2*>(&u0.y));
        s0.x += a0.x; s0.y += a0.y; s0.z += a1.x; s0.w += a1.y;
    }
    s0.x += s1.x + s2.x + s3.x;
    s0.y += s1.y + s2.y + s3.y;
    s0.z += s1.z + s2.z + s3.z;
    s0.w += s1.w + s2.w + s3.w;
    __half2 p0 = __floats2half2_rn(s0.x, s0.y);
    __half2 p1 = __floats2half2_rn(s0.z, s0.w);
    *reinterpret_cast<uint2*>(pooled + (size_t)g * HID + c) =
        make_uint2(*reinterpret_cast<uint32_t*>(&p0), *reinterpret_cast<uint32_t*>(&p1));
}

// ---------------------------------------------------------------------------
extern "C" void kernel_launch(void* const* d_in, const int* in_sizes, int n_in,
                              void* d_out, int out_size)
{
    const float* x   = (const float*)d_in[0];
    const int*   seg = (const int*)  d_in[1];
    const float* W1  = (const float*)d_in[2];
    const float* b1  = (const float*)d_in[3];
    const float* W2  = (const float*)d_in[4];
    const float* b2  = (const float*)d_in[5];
    const float* Wg1 = (const float*)d_in[6];
    const float* bg1 = (const float*)d_in[7];
    const float* Wg2 = (const float*)d_in[8];
    const float* bg2 = (const float*)d_in[9];
    float* out = (float*)d_out;

    __half *x16, *h1, *h2, *pooled, *g1, *w1t, *w2t, *wg1t, *wg2t;
    cudaGetSymbolAddress((void**)&x16, g_x16);
    cudaGetSymbolAddress((void**)&h1, g_h1);
    cudaGetSymbolAddress((void**)&h2, g_h2);
    cudaGetSymbolAddress((void**)&pooled, g_pooled);
    cudaGetSymbolAddress((void**)&g1, g_g1);
    cudaGetSymbolAddress((void**)&w1t, g_w1t);
    cudaGetSymbolAddress((void**)&w2t, g_w2t);
    cudaGetSymbolAddress((void**)&wg1t, g_wg1t);
    cudaGetSymbolAddress((void**)&wg2t, g_wg2t);

    cudaFuncSetAttribute(hgemm<true, true>,
                         cudaFuncAttributeMaxDynamicSharedMemorySize, HG_SMEM);
    cudaFuncSetAttribute(hgemm<false, false>,
                         cudaFuncAttributeMaxDynamicSharedMemorySize, HG_SMEM);

    // input conversion + weight transpose/convert
    f2h<<<((size_t)NN * INF / 4 + 255) / 256, 256>>>(x, x16, NN * INF);
    wtrans<<<(HID * INF + 255) / 256, 256>>>(W1, w1t, INF, HID);
    wtrans<<<(HID * HID + 255) / 256, 256>>>(W2, w2t, HID, HID);
    wtrans<<<(HID * HID + 255) / 256, 256>>>(Wg1, wg1t, HID, HID);
    wtrans<<<(OUTF * HID + 255) / 256, 256>>>(Wg2, wg2t, HID, OUTF);

    // node MLP (fp16 tensor cores, fp32 accumulate)
    hgemm<true, true><<<dim3(HID / 128, (NN + 127) / 128), 256, HG_SMEM>>>(
        x16, w1t, b1, h1, NN, HID, INF);
    hgemm<true, true><<<dim3(HID / 128, (NN + 127) / 128), 256, HG_SMEM>>>(
        h1, w2t, b2, h2, NN, HID, HID);

    // readout
    segment_pool<<<NG, 128>>>(h2, seg, pooled, NN);

    // graph MLP
    hgemm<true, true><<<dim3(HID / 128, NG / 128), 256, HG_SMEM>>>(
        pooled, wg1t, bg1, g1, NG, HID, HID);
    hgemm<false, false><<<dim3(OUTF / 128, NG / 128), 256, HG_SMEM>>>(
        g1, wg2t, bg2, out, NG, OUTF, HID);
}

// round 13
// speedup vs baseline: 1.0359x; 1.0359x over previous
#include <cuda_runtime.h>
#include <cuda_fp16.h>
#include <cstdint>

#define NN 200000
#define NG 2048
#define INF 256
#define HID 512
#define OUTF 256

// ---------------- scratch (__device__ globals: allocation-free rule) ----------
__device__ __half g_x16[(size_t)NN * INF];
__device__ __half g_h1[(size_t)NN * HID];
__device__ __half g_h2[(size_t)NN * HID];
__device__ __half g_pooled[NG * HID];
__device__ __half g_g1[NG * HID];
__device__ __half g_w1t[HID * INF];
__device__ __half g_w2t[HID * HID];
__device__ __half g_wg1t[HID * HID];
__device__ __half g_wg2t[OUTF * HID];

// ---------------- PTX helpers (portable sm_80+) ----------------
__device__ __forceinline__ uint32_t smem_u32(const void* p) {
    uint32_t a;
    asm("{ .reg .u64 t; cvta.to.shared.u64 t, %1; cvt.u32.u64 %0, t; }" : "=r"(a) : "l"(p));
    return a;
}
__device__ __forceinline__ void cp_async16(uint32_t dst, const void* src, int src_bytes) {
    asm volatile("cp.async.cg.shared.global [%0], [%1], 16, %2;"
                 :: "r"(dst), "l"(src), "r"(src_bytes) : "memory");
}
__device__ __forceinline__ void cp_commit() {
    asm volatile("cp.async.commit_group;" ::: "memory");
}
__device__ __forceinline__ void cp_wait1() {
    asm volatile("cp.async.wait_group 1;" ::: "memory");
}
__device__ __forceinline__ void ldsm4(uint32_t* r, uint32_t addr) {
    asm volatile("ldmatrix.sync.aligned.m8n8.x4.shared.b16 {%0,%1,%2,%3}, [%4];"
                 : "=r"(r[0]), "=r"(r[1]), "=r"(r[2]), "=r"(r[3]) : "r"(addr));
}
__device__ __forceinline__ void ldsm2(uint32_t* r, uint32_t addr) {
    asm volatile("ldmatrix.sync.aligned.m8n8.x2.shared.b16 {%0,%1}, [%2];"
                 : "=r"(r[0]), "=r"(r[1]) : "r"(addr));
}
__device__ __forceinline__ void mma16816(float* d, const uint32_t* a, const uint32_t* b) {
    asm volatile(
        "mma.sync.aligned.m16n8k16.row.col.f32.f16.f16.f32 "
        "{%0,%1,%2,%3}, {%4,%5,%6,%7}, {%8,%9}, {%0,%1,%2,%3};"
        : "+f"(d[0]), "+f"(d[1]), "+f"(d[2]), "+f"(d[3])
        : "r"(a[0]), "r"(a[1]), "r"(a[2]), "r"(a[3]), "r"(b[0]), "r"(b[1]));
}

// ---------------------------------------------------------------------------
// fp16 tensor-core GEMM with cp.async 3-stage pipeline.
// EXACT R7 configuration (best measured: 630.8us) — do not perturb.
// C[M,N] = act(A[M,K] @ Bt^T + bias);  A,Bt fp16 row-major [*,K].
// Tile BM=128, BN=128, BK=64; 256 threads (8 warps, 2x4); 3 x 32KB smem.
// ---------------------------------------------------------------------------
#define HG_STAGE 32768
#define HG_SMEM  (3 * HG_STAGE)

template <bool RELU, bool OUT_HALF>
__global__ __launch_bounds__(256, 2) void hgemm(
    const __half* __restrict__ A, const __half* __restrict__ Bt,
    const float* __restrict__ bias, void* __restrict__ Cv,
    int M, int N, int K)
{
    extern __shared__ char smem[];
    const uint32_t sbase = smem_u32(smem);
    const int tid = threadIdx.x, wid = tid >> 5, lane = tid & 31;
    const int wm = wid >> 2, wn = wid & 3;      // warp grid 2 x 4 (64x32 per warp)
    const int rowBase = blockIdx.y * 128, colBase = blockIdx.x * 128;

    float acc[4][4][4];
#pragma unroll
    for (int i = 0; i < 4; ++i)
#pragma unroll
        for (int j = 0; j < 4; ++j)
#pragma unroll
            for (int k = 0; k < 4; ++k) acc[i][j][k] = 0.0f;

    const int a_row = lane & 15;
    const int a_kb  = (lane >> 4) << 4;
    const int b_row = lane & 7;
    const int b_kb  = (lane & 8) << 1;
    const int nc = K >> 6;

    auto issue = [&](int c) {
        const int stage = c % 3;
        const uint32_t stA = sbase + stage * HG_STAGE;
        const uint32_t stB = stA + 16384;
        const int k0 = c << 6;
#pragma unroll
        for (int j = 0; j < 4; ++j) {           // A: 128 rows x 128B
            int idx = j * 256 + tid, r = idx >> 3, q = idx & 7;
            int gr = rowBase + r;
            int sz = (gr < M) ? 16 : 0;
            if (gr >= M) gr = M - 1;            // safe address, zero-filled
            uint32_t dst = stA + r * 128 + ((q * 16) ^ ((r & 7) << 4));
            cp_async16(dst, A + (size_t)gr * K + k0 + q * 8, sz);
        }
#pragma unroll
        for (int j = 0; j < 4; ++j) {           // B: 128 rows x 128B
            int idx = j * 256 + tid, r = idx >> 3, q = idx & 7;
            uint32_t dst = stB + r * 128 + ((q * 16) ^ ((r & 7) << 4));
            cp_async16(dst, Bt + (size_t)(colBase + r) * K + k0 + q * 8, 16);
        }
        cp_commit();
    };

    issue(0);
    issue(1);

    for (int c = 0; c < nc; ++c) {
        cp_wait1();                 // stage c resident
        __syncthreads();

        const uint32_t baseA = sbase + (c % 3) * HG_STAGE;
        const uint32_t baseB = baseA + 16384;
#pragma unroll
        for (int ks = 0; ks < 4; ++ks) {
            uint32_t af[4][4], bf[4][2];
#pragma unroll
            for (int mt = 0; mt < 4; ++mt) {
                int row = wm * 64 + mt * 16 + a_row;
                ldsm4(af[mt], baseA + row * 128 + ((ks * 32 + a_kb) ^ ((row & 7) << 4)));
            }
#pragma unroll
            for (int nt = 0; nt < 4; ++nt) {
                int row = wn * 32 + nt * 8 + b_row;
                ldsm2(bf[nt], baseB + row * 128 + ((ks * 32 + b_kb) ^ ((row & 7) << 4)));
            }
#pragma unroll
            for (int mt = 0; mt < 4; ++mt)
#pragma unroll
                for (int nt = 0; nt < 4; ++nt)
                    mma16816(acc[mt][nt], af[mt], bf[nt]);
        }
        if (c + 2 < nc) issue(c + 2);
        // next iteration's __syncthreads (after cp_wait1) protects stage reuse
    }

    // ---- epilogue ----
    const int qr = lane >> 2, qc = (lane & 3) * 2;
#pragma unroll
    for (int nt = 0; nt < 4; ++nt) {
        const int cc = colBase + wn * 32 + nt * 8 + qc;
        const float2 bv = *reinterpret_cast<const float2*>(bias + cc);
#pragma unroll
        for (int mt = 0; mt < 4; ++mt) {
            const int r0 = rowBase + wm * 64 + mt * 16 + qr;
            float x0 = acc[mt][nt][0] + bv.x, x1 = acc[mt][nt][1] + bv.y;
            float x2 = acc[mt][nt][2] + bv.x, x3 = acc[mt][nt][3] + bv.y;
            if (RELU) {
                x0 = fmaxf(x0, 0.f); x1 = fmaxf(x1, 0.f);
                x2 = fmaxf(x2, 0.f); x3 = fmaxf(x3, 0.f);
            }
            if (OUT_HALF) {
                __half* C = (__half*)Cv;
                __half2 p0 = __floats2half2_rn(x0, x1);
                __half2 p1 = __floats2half2_rn(x2, x3);
                if (r0 < M)
                    *reinterpret_cast<uint32_t*>(C + (size_t)r0 * N + cc) =
                        *reinterpret_cast<uint32_t*>(&p0);
                if (r0 + 8 < M)
                    *reinterpret_cast<uint32_t*>(C + (size_t)(r0 + 8) * N + cc) =
                        *reinterpret_cast<uint32_t*>(&p1);
            } else {
                float* C = (float*)Cv;
                if (r0 < M)
                    *reinterpret_cast<float2*>(C + (size_t)r0 * N + cc) = make_float2(x0, x1);
                if (r0 + 8 < M)
                    *reinterpret_cast<float2*>(C + (size_t)(r0 + 8) * N + cc) = make_float2(x2, x3);
            }
        }
    }
}

// ---------------------------------------------------------------------------
__global__ void f2h(const float* __restrict__ in, __half* __restrict__ out, int n)
{
    int i = (blockIdx.x * blockDim.x + threadIdx.x) * 4;
    if (i < n) {
        float4 v = *reinterpret_cast<const float4*>(in + i);
        __half2 p0 = __floats2half2_rn(v.x, v.y);
        __half2 p1 = __floats2half2_rn(v.z, v.w);
        *reinterpret_cast<uint2*>(out + i) =
            make_uint2(*reinterpret_cast<uint32_t*>(&p0), *reinterpret_cast<uint32_t*>(&p1));
    }
}

// ---------------------------------------------------------------------------
// Batched weight transpose+convert: all 4 weight matrices in ONE launch.
// blockIdx.y selects the matrix; same per-element work as the old wtrans.
// ---------------------------------------------------------------------------
__global__ void wtrans_all(
    const float* __restrict__ W1, __half* __restrict__ O1,     // K=INF,  N=HID
    const float* __restrict__ W2, __half* __restrict__ O2,     // K=HID,  N=HID
    const float* __restrict__ W3, __half* __restrict__ O3,     // K=HID,  N=HID
    const float* __restrict__ W4, __half* __restrict__ O4)     // K=HID,  N=OUTF
{
    const int which = blockIdx.y;
    const float* W; __half* O; int K, N;
    if (which == 0)      { W = W1; O = O1; K = INF; N = HID; }
    else if (which == 1) { W = W2; O = O2; K = HID; N = HID; }
    else if (which == 2) { W = W3; O = O3; K = HID; N = HID; }
    else                 { W = W4; O = O4; K = HID; N = OUTF; }

    int idx = blockIdx.x * blockDim.x + threadIdx.x;
    if (idx < N * K) {
        int n = idx / K, k = idx - n * K;
        O[idx] = __float2half_rn(W[(size_t)k * N + n]);
    }
}

// ---------------------------------------------------------------------------
// Segment-sum (sorted ids), fp16 in / fp32 accumulate / fp16 out.
// EXACT R7 version (simple loop; unrolled variants were noise-or-worse).
// ---------------------------------------------------------------------------
__global__ __launch_bounds__(128) void segment_pool(
    const __half* __restrict__ h, const int* __restrict__ seg,
    __half* __restrict__ pooled, int n_nodes)
{
    const int g = blockIdx.x;
    int lo = 0, hi = n_nodes;
    while (lo < hi) { int mid = (lo + hi) >> 1; if (seg[mid] < g) lo = mid + 1; else hi = mid; }
    const int start = lo;
    hi = n_nodes;
    while (lo < hi) { int mid = (lo + hi) >> 1; if (seg[mid] < g + 1) lo = mid + 1; else hi = mid; }
    const int end = lo;

    const int c = threadIdx.x << 2;
    float4 s = make_float4(0.f, 0.f, 0.f, 0.f);
    for (int r = start; r < end; ++r) {
        uint2 u = *reinterpret_cast<const uint2*>(h + (size_t)r * HID + c);
        __half2 v0 = *reinterpret_cast<__half2*>(&u.x);
        __half2 v1 = *reinterpret_cast<__half2*>(&u.y);
        float2 f0 = __half22float2(v0), f1 = __half22float2(v1);
        s.x += f0.x; s.y += f0.y; s.z += f1.x; s.w += f1.y;
    }
    __half2 p0 = __floats2half2_rn(s.x, s.y);
    __half2 p1 = __floats2half2_rn(s.z, s.w);
    *reinterpret_cast<uint2*>(pooled + (size_t)g * HID + c) =
        make_uint2(*reinterpret_cast<uint32_t*>(&p0), *reinterpret_cast<uint32_t*>(&p1));
}

// ---------------------------------------------------------------------------
extern "C" void kernel_launch(void* const* d_in, const int* in_sizes, int n_in,
                              void* d_out, int out_size)
{
    const float* x   = (const float*)d_in[0];
    const int*   seg = (const int*)  d_in[1];
    const float* W1  = (const float*)d_in[2];
    const float* b1  = (const float*)d_in[3];
    const float* W2  = (const float*)d_in[4];
    const float* b2  = (const float*)d_in[5];
    const float* Wg1 = (const float*)d_in[6];
    const float* bg1 = (const float*)d_in[7];
    const float* Wg2 = (const float*)d_in[8];
    const float* bg2 = (const float*)d_in[9];
    float* out = (float*)d_out;

    __half *x16, *h1, *h2, *pooled, *g1, *w1t, *w2t, *wg1t, *wg2t;
    cudaGetSymbolAddress((void**)&x16, g_x16);
    cudaGetSymbolAddress((void**)&h1, g_h1);
    cudaGetSymbolAddress((void**)&h2, g_h2);
    cudaGetSymbolAddress((void**)&pooled, g_pooled);
    cudaGetSymbolAddress((void**)&g1, g_g1);
    cudaGetSymbolAddress((void**)&w1t, g_w1t);
    cudaGetSymbolAddress((void**)&w2t, g_w2t);
    cudaGetSymbolAddress((void**)&wg1t, g_wg1t);
    cudaGetSymbolAddress((void**)&wg2t, g_wg2t);

    cudaFuncSetAttribute(hgemm<true, true>,
                         cudaFuncAttributeMaxDynamicSharedMemorySize, HG_SMEM);
    cudaFuncSetAttribute(hgemm<false, false>,
                         cudaFuncAttributeMaxDynamicSharedMemorySize, HG_SMEM);

    // input conversion + batched weight transpose/convert (2 launches, was 5)
    f2h<<<((size_t)NN * INF / 4 + 255) / 256, 256>>>(x, x16, NN * INF);
    wtrans_all<<<dim3((HID * HID + 255) / 256, 4), 256>>>(
        W1, w1t, W2, w2t, Wg1, wg1t, Wg2, wg2t);

    // node MLP (fp16 tensor cores, fp32 accumulate)
    hgemm<true, true><<<dim3(HID / 128, (NN + 127) / 128), 256, HG_SMEM>>>(
        x16, w1t, b1, h1, NN, HID, INF);
    hgemm<true, true><<<dim3(HID / 128, (NN + 127) / 128), 256, HG_SMEM>>>(
        h1, w2t, b2, h2, NN, HID, HID);

    // readout
    segment_pool<<<NG, 128>>>(h2, seg, pooled, NN);

    // graph MLP
    hgemm<true, true><<<dim3(HID / 128, NG / 128), 256, HG_SMEM>>>(
        pooled, wg1t, bg1, g1, NG, HID, HID);
    hgemm<false, false><<<dim3(OUTF / 128, NG / 128), 256, HG_SMEM>>>(
        g1, wg2t, bg2, out, NG, OUTF, HID);
}

// round 14
// speedup vs baseline: 1.0427x; 1.0066x over previous
#include <cuda_runtime.h>
#include <cuda_fp16.h>
#include <cstdint>

#define NN 200000
#define NG 2048
#define INF 256
#define HID 512
#define OUTF 256

// ---------------- scratch (__device__ globals: allocation-free rule) ----------
__device__ __half g_x16[(size_t)NN * INF];
__device__ __half g_h1[(size_t)NN * HID];
__device__ __half g_h2[(size_t)NN * HID];
__device__ __half g_pooled[NG * HID];
__device__ __half g_g1[NG * HID];
__device__ __half g_w1t[HID * INF];
__device__ __half g_w2t[HID * HID];
__device__ __half g_wg1t[HID * HID];
__device__ __half g_wg2t[OUTF * HID];

// ---------------- PTX helpers (portable sm_80+) ----------------
__device__ __forceinline__ uint32_t smem_u32(const void* p) {
    uint32_t a;
    asm("{ .reg .u64 t; cvta.to.shared.u64 t, %1; cvt.u32.u64 %0, t; }" : "=r"(a) : "l"(p));
    return a;
}
__device__ __forceinline__ void cp_async16(uint32_t dst, const void* src, int src_bytes) {
    asm volatile("cp.async.cg.shared.global [%0], [%1], 16, %2;"
                 :: "r"(dst), "l"(src), "r"(src_bytes) : "memory");
}
__device__ __forceinline__ void cp_commit() {
    asm volatile("cp.async.commit_group;" ::: "memory");
}
__device__ __forceinline__ void cp_wait1() {
    asm volatile("cp.async.wait_group 1;" ::: "memory");
}
__device__ __forceinline__ void ldsm4(uint32_t* r, uint32_t addr) {
    asm volatile("ldmatrix.sync.aligned.m8n8.x4.shared.b16 {%0,%1,%2,%3}, [%4];"
                 : "=r"(r[0]), "=r"(r[1]), "=r"(r[2]), "=r"(r[3]) : "r"(addr));
}
__device__ __forceinline__ void mma16816(float* d, const uint32_t* a, const uint32_t* b) {
    asm volatile(
        "mma.sync.aligned.m16n8k16.row.col.f32.f16.f16.f32 "
        "{%0,%1,%2,%3}, {%4,%5,%6,%7}, {%8,%9}, {%0,%1,%2,%3};"
        : "+f"(d[0]), "+f"(d[1]), "+f"(d[2]), "+f"(d[3])
        : "r"(a[0]), "r"(a[1]), "r"(a[2]), "r"(a[3]), "r"(b[0]), "r"(b[1]));
}

// ---------------------------------------------------------------------------
// fp16 tensor-core GEMM with cp.async 3-stage pipeline.
// R13 base + (a) B fragments via ldmatrix.x4 pairs (8->6 shared-load
// instructions per ks on the binding L1 path), (b) issue(c+2) hoisted ahead
// of compute for full copy/compute overlap. Numerics identical to R7/R13.
// C[M,N] = act(A[M,K] @ Bt^T + bias);  A,Bt fp16 row-major [*,K].
// Tile BM=128, BN=128, BK=64; 256 threads (8 warps, 2x4); 3 x 32KB smem.
// ---------------------------------------------------------------------------
#define HG_STAGE 32768
#define HG_SMEM  (3 * HG_STAGE)

template <bool RELU, bool OUT_HALF>
__global__ __launch_bounds__(256, 2) void hgemm(
    const __half* __restrict__ A, const __half* __restrict__ Bt,
    const float* __restrict__ bias, void* __restrict__ Cv,
    int M, int N, int K)
{
    extern __shared__ char smem[];
    const uint32_t sbase = smem_u32(smem);
    const int tid = threadIdx.x, wid = tid >> 5, lane = tid & 31;
    const int wm = wid >> 2, wn = wid & 3;      // warp grid 2 x 4 (64x32 per warp)
    const int rowBase = blockIdx.y * 128, colBase = blockIdx.x * 128;

    float acc[4][4][4];
#pragma unroll
    for (int i = 0; i < 4; ++i)
#pragma unroll
        for (int j = 0; j < 4; ++j)
#pragma unroll
            for (int k = 0; k < 4; ++k) acc[i][j][k] = 0.0f;

    // A ldmatrix lane constants (x4: m16 rows + k-halves)
    const int a_row = lane & 15;
    const int a_kb  = (lane >> 4) << 4;
    // B ldmatrix.x4 lane constants: matrix index m = lane>>3
    //   m=0: nt rows,   kb 0    -> bf[nt][0]
    //   m=1: nt rows,   kb 16   -> bf[nt][1]
    //   m=2: nt+1 rows, kb 0    -> bf[nt+1][0]
    //   m=3: nt+1 rows, kb 16   -> bf[nt+1][1]
    const int b_m    = lane >> 3;
    const int b_rowl = ((b_m >> 1) << 3) + (lane & 7);  // row within the 16-row pair
    const int b_kb   = (b_m & 1) << 4;
    const int nc = K >> 6;

    auto issue = [&](int c) {
        const int stage = c % 3;
        const uint32_t stA = sbase + stage * HG_STAGE;
        const uint32_t stB = stA + 16384;
        const int k0 = c << 6;
#pragma unroll
        for (int j = 0; j < 4; ++j) {           // A: 128 rows x 128B
            int idx = j * 256 + tid, r = idx >> 3, q = idx & 7;
            int gr = rowBase + r;
            int sz = (gr < M) ? 16 : 0;
            if (gr >= M) gr = M - 1;            // safe address, zero-filled
            uint32_t dst = stA + r * 128 + ((q * 16) ^ ((r & 7) << 4));
            cp_async16(dst, A + (size_t)gr * K + k0 + q * 8, sz);
        }
#pragma unroll
        for (int j = 0; j < 4; ++j) {           // B: 128 rows x 128B
            int idx = j * 256 + tid, r = idx >> 3, q = idx & 7;
            uint32_t dst = stB + r * 128 + ((q * 16) ^ ((r & 7) << 4));
            cp_async16(dst, Bt + (size_t)(colBase + r) * K + k0 + q * 8, 16);
        }
        cp_commit();
    };

    issue(0);
    issue(1);

    for (int c = 0; c < nc; ++c) {
        cp_wait1();                 // stage c resident
        __syncthreads();            // also fences stage (c-1) reuse by issue below
        if (c + 2 < nc) issue(c + 2);   // full overlap with this chunk's compute

        const uint32_t baseA = sbase + (c % 3) * HG_STAGE;
        const uint32_t baseB = baseA + 16384;
#pragma unroll
        for (int ks = 0; ks < 4; ++ks) {
            uint32_t af[4][4], bf[4][2];
#pragma unroll
            for (int mt = 0; mt < 4; ++mt) {
                int row = wm * 64 + mt * 16 + a_row;
                ldsm4(af[mt], baseA + row * 128 + ((ks * 32 + a_kb) ^ ((row & 7) << 4)));
            }
#pragma unroll
            for (int ntp = 0; ntp < 2; ++ntp) { // 2 x ldsm4 covers 4 B fragments
                int row = wn * 32 + ntp * 16 + b_rowl;
                uint32_t r4[4];
                ldsm4(r4, baseB + row * 128 + ((ks * 32 + b_kb) ^ ((row & 7) << 4)));
                bf[ntp * 2 + 0][0] = r4[0];
                bf[ntp * 2 + 0][1] = r4[1];
                bf[ntp * 2 + 1][0] = r4[2];
                bf[ntp * 2 + 1][1] = r4[3];
            }
#pragma unroll
            for (int mt = 0; mt < 4; ++mt)
#pragma unroll
                for (int nt = 0; nt < 4; ++nt)
                    mma16816(acc[mt][nt], af[mt], bf[nt]);
        }
    }

    // ---- epilogue ----
    const int qr = lane >> 2, qc = (lane & 3) * 2;
#pragma unroll
    for (int nt = 0; nt < 4; ++nt) {
        const int cc = colBase + wn * 32 + nt * 8 + qc;
        const float2 bv = *reinterpret_cast<const float2*>(bias + cc);
#pragma unroll
        for (int mt = 0; mt < 4; ++mt) {
            const int r0 = rowBase + wm * 64 + mt * 16 + qr;
            float x0 = acc[mt][nt][0] + bv.x, x1 = acc[mt][nt][1] + bv.y;
            float x2 = acc[mt][nt][2] + bv.x, x3 = acc[mt][nt][3] + bv.y;
            if (RELU) {
                x0 = fmaxf(x0, 0.f); x1 = fmaxf(x1, 0.f);
                x2 = fmaxf(x2, 0.f); x3 = fmaxf(x3, 0.f);
            }
            if (OUT_HALF) {
                __half* C = (__half*)Cv;
                __half2 p0 = __floats2half2_rn(x0, x1);
                __half2 p1 = __floats2half2_rn(x2, x3);
                if (r0 < M)
                    *reinterpret_cast<uint32_t*>(C + (size_t)r0 * N + cc) =
                        *reinterpret_cast<uint32_t*>(&p0);
                if (r0 + 8 < M)
                    *reinterpret_cast<uint32_t*>(C + (size_t)(r0 + 8) * N + cc) =
                        *reinterpret_cast<uint32_t*>(&p1);
            } else {
                float* C = (float*)Cv;
                if (r0 < M)
                    *reinterpret_cast<float2*>(C + (size_t)r0 * N + cc) = make_float2(x0, x1);
                if (r0 + 8 < M)
                    *reinterpret_cast<float2*>(C + (size_t)(r0 + 8) * N + cc) = make_float2(x2, x3);
            }
        }
    }
}

// ---------------------------------------------------------------------------
__global__ void f2h(const float* __restrict__ in, __half* __restrict__ out, int n)
{
    int i = (blockIdx.x * blockDim.x + threadIdx.x) * 4;
    if (i < n) {
        float4 v = *reinterpret_cast<const float4*>(in + i);
        __half2 p0 = __floats2half2_rn(v.x, v.y);
        __half2 p1 = __floats2half2_rn(v.z, v.w);
        *reinterpret_cast<uint2*>(out + i) =
            make_uint2(*reinterpret_cast<uint32_t*>(&p0), *reinterpret_cast<uint32_t*>(&p1));
    }
}

// ---------------------------------------------------------------------------
// Batched weight transpose+convert: all 4 weight matrices in ONE launch.
// ---------------------------------------------------------------------------
__global__ void wtrans_all(
    const float* __restrict__ W1, __half* __restrict__ O1,     // K=INF,  N=HID
    const float* __restrict__ W2, __half* __restrict__ O2,     // K=HID,  N=HID
    const float* __restrict__ W3, __half* __restrict__ O3,     // K=HID,  N=HID
    const float* __restrict__ W4, __half* __restrict__ O4)     // K=HID,  N=OUTF
{
    const int which = blockIdx.y;
    const float* W; __half* O; int K, N;
    if (which == 0)      { W = W1; O = O1; K = INF; N = HID; }
    else if (which == 1) { W = W2; O = O2; K = HID; N = HID; }
    else if (which == 2) { W = W3; O = O3; K = HID; N = HID; }
    else                 { W = W4; O = O4; K = HID; N = OUTF; }

    int idx = blockIdx.x * blockDim.x + threadIdx.x;
    if (idx < N * K) {
        int n = idx / K, k = idx - n * K;
        O[idx] = __float2half_rn(W[(size_t)k * N + n]);
    }
}

// ---------------------------------------------------------------------------
// Segment-sum (sorted ids), fp16 in / fp32 accumulate / fp16 out (R7 version).
// ---------------------------------------------------------------------------
__global__ __launch_bounds__(128) void segment_pool(
    const __half* __restrict__ h, const int* __restrict__ seg,
    __half* __restrict__ pooled, int n_nodes)
{
    const int g = blockIdx.x;
    int lo = 0, hi = n_nodes;
    while (lo < hi) { int mid = (lo + hi) >> 1; if (seg[mid] < g) lo = mid + 1; else hi = mid; }
    const int start = lo;
    hi = n_nodes;
    while (lo < hi) { int mid = (lo + hi) >> 1; if (seg[mid] < g + 1) lo = mid + 1; else hi = mid; }
    const int end = lo;

    const int c = threadIdx.x << 2;
    float4 s = make_float4(0.f, 0.f, 0.f, 0.f);
    for (int r = start; r < end; ++r) {
        uint2 u = *reinterpret_cast<const uint2*>(h + (size_t)r * HID + c);
        __half2 v0 = *reinterpret_cast<__half2*>(&u.x);
        __half2 v1 = *reinterpret_cast<__half2*>(&u.y);
        float2 f0 = __half22float2(v0), f1 = __half22float2(v1);
        s.x += f0.x; s.y += f0.y; s.z += f1.x; s.w += f1.y;
    }
    __half2 p0 = __floats2half2_rn(s.x, s.y);
    __half2 p1 = __floats2half2_rn(s.z, s.w);
    *reinterpret_cast<uint2*>(pooled + (size_t)g * HID + c) =
        make_uint2(*reinterpret_cast<uint32_t*>(&p0), *reinterpret_cast<uint32_t*>(&p1));
}

// ---------------------------------------------------------------------------
extern "C" void kernel_launch(void* const* d_in, const int* in_sizes, int n_in,
                              void* d_out, int out_size)
{
    const float* x   = (const float*)d_in[0];
    const int*   seg = (const int*)  d_in[1];
    const float* W1  = (const float*)d_in[2];
    const float* b1  = (const float*)d_in[3];
    const float* W2  = (const float*)d_in[4];
    const float* b2  = (const float*)d_in[5];
    const float* Wg1 = (const float*)d_in[6];
    const float* bg1 = (const float*)d_in[7];
    const float* Wg2 = (const float*)d_in[8];
    const float* bg2 = (const float*)d_in[9];
    float* out = (float*)d_out;

    __half *x16, *h1, *h2, *pooled, *g1, *w1t, *w2t, *wg1t, *wg2t;
    cudaGetSymbolAddress((void**)&x16, g_x16);
    cudaGetSymbolAddress((void**)&h1, g_h1);
    cudaGetSymbolAddress((void**)&h2, g_h2);
    cudaGetSymbolAddress((void**)&pooled, g_pooled);
    cudaGetSymbolAddress((void**)&g1, g_g1);
    cudaGetSymbolAddress((void**)&w1t, g_w1t);
    cudaGetSymbolAddress((void**)&w2t, g_w2t);
    cudaGetSymbolAddress((void**)&wg1t, g_wg1t);
    cudaGetSymbolAddress((void**)&wg2t, g_wg2t);

    cudaFuncSetAttribute(hgemm<true, true>,
                         cudaFuncAttributeMaxDynamicSharedMemorySize, HG_SMEM);
    cudaFuncSetAttribute(hgemm<false, false>,
                         cudaFuncAttributeMaxDynamicSharedMemorySize, HG_SMEM);

    // input conversion + batched weight transpose/convert
    f2h<<<((size_t)NN * INF / 4 + 255) / 256, 256>>>(x, x16, NN * INF);
    wtrans_all<<<dim3((HID * HID + 255) / 256, 4), 256>>>(
        W1, w1t, W2, w2t, Wg1, wg1t, Wg2, wg2t);

    // node MLP (fp16 tensor cores, fp32 accumulate)
    hgemm<true, true><<<dim3(HID / 128, (NN + 127) / 128), 256, HG_SMEM>>>(
        x16, w1t, b1, h1, NN, HID, INF);
    hgemm<true, true><<<dim3(HID / 128, (NN + 127) / 128), 256, HG_SMEM>>>(
        h1, w2t, b2, h2, NN, HID, HID);

    // readout
    segment_pool<<<NG, 128>>>(h2, seg, pooled, NN);

    // graph MLP
    hgemm<true, true><<<dim3(HID / 128, NG / 128), 256, HG_SMEM>>>(
        pooled, wg1t, bg1, g1, NG, HID, HID);
    hgemm<false, false><<<dim3(OUTF / 128, NG / 128), 256, HG_SMEM>>>(
        g1, wg2t, bg2, out, NG, OUTF, HID);
}